// round 11
// baseline (speedup 1.0000x reference)
#include <cuda_runtime.h>
#include <math.h>

// Quanvolution: 4-qubit circuit per 2x2 patch, fixed variational unitary.
// e_w(theta) = sum_t CW[w][t] * prod_q g_{t_q}(theta_q), g = (1, cos, sin).
// CW precomputed by a tiny setup kernel (sparse 16-pair enumeration).

#define NQb 4
#define NPp 196
#define NBp 14
#define IMGd 28
#define THREADS_MAIN 224

// CW stored interleaved: g_CW4[t] = {CW_w0[t], CW_w1[t], CW_w2[t], CW_w3[t]}
__device__ float4 g_CW4[81];

static __device__ __forceinline__ int qbit(int z, int q) { return (z >> (3 - q)) & 1; }

__global__ void quanv_setup_kernel(const float* __restrict__ vp /*[2][2][4]*/) {
    __shared__ float Ur[16][16], Ui[16][16];   // [z][col]
    __shared__ float M[4][16][16];
    int tid = threadIdx.x;

    if (tid < 16) {
        float ar[16], ai[16];
#pragma unroll
        for (int z = 0; z < 16; z++) { ar[z] = (z == tid) ? 1.0f : 0.0f; ai[z] = 0.0f; }
#pragma unroll
        for (int l = 0; l < 2; l++) {
            // RY layer
#pragma unroll
            for (int w = 0; w < 4; w++) {
                float h = 0.5f * vp[l * 8 + w];
                float c = cosf(h), s = sinf(h);
                int mask = 8 >> w;
#pragma unroll
                for (int z = 0; z < 16; z++) {
                    if (!(z & mask)) {
                        int z1 = z | mask;
                        float r0 = ar[z], i0 = ai[z], r1 = ar[z1], i1 = ai[z1];
                        ar[z]  = c * r0 - s * r1;  ai[z]  = c * i0 - s * i1;
                        ar[z1] = s * r0 + c * r1;  ai[z1] = s * i0 + c * i1;
                    }
                }
            }
            // RZ layer
#pragma unroll
            for (int w = 0; w < 4; w++) {
                float h = 0.5f * vp[l * 8 + 4 + w];
                float c = cosf(h), s = sinf(h);
                int mask = 8 >> w;
#pragma unroll
                for (int z = 0; z < 16; z++) {
                    float ph_i = (z & mask) ? s : -s;   // exp(+-i h)
                    float r = ar[z], im = ai[z];
                    ar[z] = c * r - ph_i * im;
                    ai[z] = c * im + ph_i * r;
                }
            }
            // CNOT chain 0->1, 1->2, 2->3
#pragma unroll
            for (int cq = 0; cq < 3; cq++) {
                int cm = 8 >> cq, tm = 8 >> (cq + 1);
#pragma unroll
                for (int z = 0; z < 16; z++) {
                    if ((z & cm) && !(z & tm)) {
                        int z1 = z | tm;
                        float tr = ar[z], ti = ai[z];
                        ar[z] = ar[z1]; ai[z] = ai[z1];
                        ar[z1] = tr;    ai[z1] = ti;
                    }
                }
            }
        }
#pragma unroll
        for (int z = 0; z < 16; z++) { Ur[z][tid] = ar[z]; Ui[z][tid] = ai[z]; }
    }
    __syncthreads();

    // M[w][i][j] = sum_z sign_w(z) * Re(conj(U[z,i]) U[z,j])
    for (int k = tid; k < 4 * 256; k += blockDim.x) {
        int w = k >> 8, i = (k >> 4) & 15, j = k & 15;
        float acc = 0.0f;
#pragma unroll
        for (int z = 0; z < 16; z++) {
            float sgn = qbit(z, w) ? -1.0f : 1.0f;
            acc += sgn * (Ur[z][i] * Ur[z][j] + Ui[z][i] * Ui[z][j]);
        }
        M[w][i][j] = acc;
    }
    __syncthreads();

    // Sparse contraction: for fixed t, kcoef is nonzero for exactly 2 (bi,bj)
    // combos per qubit -> 16 contributing (i,j) pairs (not 256).
    //   t_q in {0,1}: bi==bj in {0,1}; coef = 0.5 (t=0) or +-0.5 (t=1, sign=bi)
    //   t_q == 2   : (bi,bj) in {(0,1),(1,0)}; coef = 0.5
    for (int k = tid; k < 4 * 81; k += blockDim.x) {
        int w = k / 81, t = k % 81;
        int td[4] = { t / 27, (t / 9) % 3, (t / 3) % 3, t % 3 };
        float acc = 0.0f;
#pragma unroll
        for (int m = 0; m < 16; m++) {
            int i = 0, j = 0;
            float coef = 1.0f;
#pragma unroll
            for (int q = 0; q < 4; q++) {
                int sel = (m >> (3 - q)) & 1;   // which of the 2 combos
                int tq = td[q];
                int bi, bj; float c;
                if (tq == 2) { bi = sel; bj = 1 - sel; c = 0.5f; }
                else         { bi = sel; bj = sel;
                               c = (tq == 0) ? 0.5f : (sel ? -0.5f : 0.5f); }
                i |= bi << (3 - q);
                j |= bj << (3 - q);
                coef *= c;
            }
            acc += M[w][i][j] * coef;
        }
        // interleaved layout [t][w]
        ((float*)g_CW4)[t * 4 + w] = acc;
    }
}

__global__ __launch_bounds__(THREADS_MAIN) void quanv_main_kernel(
    const float* __restrict__ x, const float* __restrict__ W,
    const float* __restrict__ bias, float* __restrict__ out) {
    __shared__ __align__(16) float xs[784];
    __shared__ __align__(16) float4 cw4[81];
    __shared__ __align__(16) float fs[784];
    __shared__ float logits[10];

    int b = blockIdx.x, tid = threadIdx.x;

    if (tid < 196) reinterpret_cast<float4*>(xs)[tid] =
        reinterpret_cast<const float4*>(x + b * 784)[tid];
    if (tid < 81) cw4[tid] = g_CW4[tid];
    __syncthreads();

    int p = tid;
    if (p < NPp) {
        int pi = p / NBp, pj = p % NBp;
        const float* xp = &xs[pi * 2 * IMGd + pj * 2];
        float th0 = xp[0], th1 = xp[1], th2 = xp[IMGd], th3 = xp[IMGd + 1];

        float g0[3], g1[3], g2[3], g3[3];
        g0[0] = 1.0f; __sincosf(th0, &g0[2], &g0[1]);
        g1[0] = 1.0f; __sincosf(th1, &g1[2], &g1[1]);
        g2[0] = 1.0f; __sincosf(th2, &g2[2], &g2[1]);
        g3[0] = 1.0f; __sincosf(th3, &g3[2], &g3[1]);

        float P01[9], P23[9];
#pragma unroll
        for (int a = 0; a < 3; a++)
#pragma unroll
            for (int c = 0; c < 3; c++) {
                P01[a * 3 + c] = g0[a] * g1[c];
                P23[a * 3 + c] = g2[a] * g3[c];
            }

        float ax = 0.f, ay = 0.f, az = 0.f, aw = 0.f;
#pragma unroll
        for (int u = 0; u < 9; u++) {
            // stage 1: tmp = sum_v CW4[u*9+v] * P23[v]
            float tx = 0.f, ty = 0.f, tz = 0.f, tw = 0.f;
#pragma unroll
            for (int v = 0; v < 9; v++) {
                float4 c4 = cw4[u * 9 + v];
                float pv = P23[v];
                tx += c4.x * pv; ty += c4.y * pv;
                tz += c4.z * pv; tw += c4.w * pv;
            }
            // stage 2: acc += P01[u] * tmp
            float pu = P01[u];
            ax += pu * tx; ay += pu * ty; az += pu * tz; aw += pu * tw;
        }
        reinterpret_cast<float4*>(fs)[p] = make_float4(ax, ay, az, aw);
    }
    __syncthreads();

    int warp = tid >> 5, lane = tid & 31;
    if (warp < 5) {
#pragma unroll
        for (int r = 0; r < 2; r++) {
            int c = warp * 2 + r;
            const float* wr = &W[c * 784];
            float acc = 0.0f;
#pragma unroll 4
            for (int i = lane; i < 784; i += 32) acc += fs[i] * __ldg(&wr[i]);
#pragma unroll
            for (int o = 16; o > 0; o >>= 1) acc += __shfl_xor_sync(0xffffffffu, acc, o);
            if (lane == 0) logits[c] = acc + __ldg(&bias[c]);
        }
    }
    __syncthreads();

    if (tid == 0) {
        float m = -1e30f;
#pragma unroll
        for (int c = 0; c < 10; c++) m = fmaxf(m, logits[c]);
        float s = 0.0f;
#pragma unroll
        for (int c = 0; c < 10; c++) s += expf(logits[c] - m);
        float lg = logf(s) + m;
#pragma unroll
        for (int c = 0; c < 10; c++) out[b * 10 + c] = logits[c] - lg;
    }
}

extern "C" void kernel_launch(void* const* d_in, const int* in_sizes, int n_in,
                              void* d_out, int out_size) {
    const float* x    = (const float*)d_in[0];   // (2048, 28, 28)
    const float* vp   = (const float*)d_in[1];   // (2, 2, 4)
    const float* W    = (const float*)d_in[2];   // (10, 784)
    const float* bias = (const float*)d_in[3];   // (10,)
    float* out = (float*)d_out;                  // (2048, 10)

    int B = in_sizes[0] / (IMGd * IMGd);

    quanv_setup_kernel<<<1, 512>>>(vp);
    quanv_main_kernel<<<B, THREADS_MAIN>>>(x, W, bias, out);
}

// round 13
// speedup vs baseline: 1.0011x; 1.0011x over previous
#include <cuda_runtime.h>
#include <math.h>

// Quanvolution: 4-qubit circuit per 2x2 patch, fixed variational unitary.
// e_w(theta) = sum_t CW[w][t] * prod_q g_{t_q}(theta_q), g = (1, cos, sin).
// CW precomputed by a tiny setup kernel (sparse 16-pair enumeration).
// Main kernel: 2 images per block; ALL __syncthreads() at uniform block scope.

#define NQb 4
#define NPp 196
#define NBp 14
#define IMGd 28
#define THREADS_MAIN 224

// CW stored interleaved: g_CW4[t] = {CW_w0[t], CW_w1[t], CW_w2[t], CW_w3[t]}
__device__ float4 g_CW4[81];

static __device__ __forceinline__ int qbit(int z, int q) { return (z >> (3 - q)) & 1; }

__global__ void quanv_setup_kernel(const float* __restrict__ vp /*[2][2][4]*/) {
    __shared__ float Ur[16][16], Ui[16][16];   // [z][col]
    __shared__ float M[4][16][16];
    int tid = threadIdx.x;

    if (tid < 16) {
        float ar[16], ai[16];
#pragma unroll
        for (int z = 0; z < 16; z++) { ar[z] = (z == tid) ? 1.0f : 0.0f; ai[z] = 0.0f; }
#pragma unroll
        for (int l = 0; l < 2; l++) {
            // RY layer
#pragma unroll
            for (int w = 0; w < 4; w++) {
                float h = 0.5f * vp[l * 8 + w];
                float c = cosf(h), s = sinf(h);
                int mask = 8 >> w;
#pragma unroll
                for (int z = 0; z < 16; z++) {
                    if (!(z & mask)) {
                        int z1 = z | mask;
                        float r0 = ar[z], i0 = ai[z], r1 = ar[z1], i1 = ai[z1];
                        ar[z]  = c * r0 - s * r1;  ai[z]  = c * i0 - s * i1;
                        ar[z1] = s * r0 + c * r1;  ai[z1] = s * i0 + c * i1;
                    }
                }
            }
            // RZ layer
#pragma unroll
            for (int w = 0; w < 4; w++) {
                float h = 0.5f * vp[l * 8 + 4 + w];
                float c = cosf(h), s = sinf(h);
                int mask = 8 >> w;
#pragma unroll
                for (int z = 0; z < 16; z++) {
                    float ph_i = (z & mask) ? s : -s;   // exp(+-i h)
                    float r = ar[z], im = ai[z];
                    ar[z] = c * r - ph_i * im;
                    ai[z] = c * im + ph_i * r;
                }
            }
            // CNOT chain 0->1, 1->2, 2->3
#pragma unroll
            for (int cq = 0; cq < 3; cq++) {
                int cm = 8 >> cq, tm = 8 >> (cq + 1);
#pragma unroll
                for (int z = 0; z < 16; z++) {
                    if ((z & cm) && !(z & tm)) {
                        int z1 = z | tm;
                        float tr = ar[z], ti = ai[z];
                        ar[z] = ar[z1]; ai[z] = ai[z1];
                        ar[z1] = tr;    ai[z1] = ti;
                    }
                }
            }
        }
#pragma unroll
        for (int z = 0; z < 16; z++) { Ur[z][tid] = ar[z]; Ui[z][tid] = ai[z]; }
    }
    __syncthreads();

    // M[w][i][j] = sum_z sign_w(z) * Re(conj(U[z,i]) U[z,j])
    for (int k = tid; k < 4 * 256; k += blockDim.x) {
        int w = k >> 8, i = (k >> 4) & 15, j = k & 15;
        float acc = 0.0f;
#pragma unroll
        for (int z = 0; z < 16; z++) {
            float sgn = qbit(z, w) ? -1.0f : 1.0f;
            acc += sgn * (Ur[z][i] * Ur[z][j] + Ui[z][i] * Ui[z][j]);
        }
        M[w][i][j] = acc;
    }
    __syncthreads();

    // Sparse contraction: for fixed t, kcoef is nonzero for exactly 2 (bi,bj)
    // combos per qubit -> 16 contributing (i,j) pairs (not 256).
    for (int k = tid; k < 4 * 81; k += blockDim.x) {
        int w = k / 81, t = k % 81;
        int td[4] = { t / 27, (t / 9) % 3, (t / 3) % 3, t % 3 };
        float acc = 0.0f;
#pragma unroll
        for (int m = 0; m < 16; m++) {
            int i = 0, j = 0;
            float coef = 1.0f;
#pragma unroll
            for (int q = 0; q < 4; q++) {
                int sel = (m >> (3 - q)) & 1;
                int tq = td[q];
                int bi, bj; float c;
                if (tq == 2) { bi = sel; bj = 1 - sel; c = 0.5f; }
                else         { bi = sel; bj = sel;
                               c = (tq == 0) ? 0.5f : (sel ? -0.5f : 0.5f); }
                i |= bi << (3 - q);
                j |= bj << (3 - q);
                coef *= c;
            }
            acc += M[w][i][j] * coef;
        }
        ((float*)g_CW4)[t * 4 + w] = acc;   // interleaved layout [t][w]
    }
}

__global__ __launch_bounds__(THREADS_MAIN) void quanv_main_kernel(
    const float* __restrict__ x, const float* __restrict__ W,
    const float* __restrict__ bias, float* __restrict__ out, int B) {
    __shared__ __align__(16) float4 cw4[81];
    __shared__ __align__(16) float fs[2][784];
    __shared__ float logits[2][10];

    int b0 = blockIdx.x * 2;
    int b1 = (b0 + 1 < B) ? (b0 + 1) : b0;       // clamp (duplicate work, guarded write)
    int tid = threadIdx.x;

    if (tid < 81) cw4[tid] = g_CW4[tid];

    int p = tid;
    bool active = (p < NPp);

    // ---- phase 1: guarded loads + P-array construction (no barriers here) ----
    float P01a[9], P23a[9], P01b[9], P23b[9];
    if (active) {
        int pi = p / NBp, pj = p % NBp;
        int off = pi * 2 * IMGd + pj * 2;

        // coalesced direct global loads: consecutive pj -> contiguous float2
        float2 r0a = __ldg((const float2*)(x + b0 * 784 + off));
        float2 r1a = __ldg((const float2*)(x + b0 * 784 + off + IMGd));
        float2 r0b = __ldg((const float2*)(x + b1 * 784 + off));
        float2 r1b = __ldg((const float2*)(x + b1 * 784 + off + IMGd));

        float g0[3], g1[3], g2[3], g3[3];
        float h0[3], h1[3], h2[3], h3[3];
        g0[0] = 1.0f; __sincosf(r0a.x, &g0[2], &g0[1]);
        g1[0] = 1.0f; __sincosf(r0a.y, &g1[2], &g1[1]);
        g2[0] = 1.0f; __sincosf(r1a.x, &g2[2], &g2[1]);
        g3[0] = 1.0f; __sincosf(r1a.y, &g3[2], &g3[1]);
        h0[0] = 1.0f; __sincosf(r0b.x, &h0[2], &h0[1]);
        h1[0] = 1.0f; __sincosf(r0b.y, &h1[2], &h1[1]);
        h2[0] = 1.0f; __sincosf(r1b.x, &h2[2], &h2[1]);
        h3[0] = 1.0f; __sincosf(r1b.y, &h3[2], &h3[1]);

#pragma unroll
        for (int a = 0; a < 3; a++)
#pragma unroll
            for (int c = 0; c < 3; c++) {
                P01a[a * 3 + c] = g0[a] * g1[c];
                P23a[a * 3 + c] = g2[a] * g3[c];
                P01b[a * 3 + c] = h0[a] * h1[c];
                P23b[a * 3 + c] = h2[a] * h3[c];
            }
    }

    __syncthreads();   // uniform: cw4 staging complete

    // ---- phase 2: trilinear contraction for both images ----
    if (active) {
        float ax0 = 0.f, ay0 = 0.f, az0 = 0.f, aw0 = 0.f;
        float ax1 = 0.f, ay1 = 0.f, az1 = 0.f, aw1 = 0.f;
#pragma unroll
        for (int u = 0; u < 9; u++) {
            float tx0 = 0.f, ty0 = 0.f, tz0 = 0.f, tw0 = 0.f;
            float tx1 = 0.f, ty1 = 0.f, tz1 = 0.f, tw1 = 0.f;
#pragma unroll
            for (int v = 0; v < 9; v++) {
                float4 c4 = cw4[u * 9 + v];
                float pa = P23a[v], pb = P23b[v];
                tx0 += c4.x * pa; ty0 += c4.y * pa; tz0 += c4.z * pa; tw0 += c4.w * pa;
                tx1 += c4.x * pb; ty1 += c4.y * pb; tz1 += c4.z * pb; tw1 += c4.w * pb;
            }
            float pua = P01a[u], pub = P01b[u];
            ax0 += pua * tx0; ay0 += pua * ty0; az0 += pua * tz0; aw0 += pua * tw0;
            ax1 += pub * tx1; ay1 += pub * ty1; az1 += pub * tz1; aw1 += pub * tw1;
        }
        reinterpret_cast<float4*>(fs[0])[p] = make_float4(ax0, ay0, az0, aw0);
        reinterpret_cast<float4*>(fs[1])[p] = make_float4(ax1, ay1, az1, aw1);
    }

    __syncthreads();   // uniform: features ready

    int warp = tid >> 5, lane = tid & 31;
    if (warp < 5) {
        int c0 = warp * 2, c1 = c0 + 1;
        const float* w0 = &W[c0 * 784];
        const float* w1 = &W[c1 * 784];
        float a00 = 0.f, a01 = 0.f, a10 = 0.f, a11 = 0.f;
#pragma unroll 4
        for (int i = lane; i < 784; i += 32) {
            float wv0 = __ldg(&w0[i]), wv1 = __ldg(&w1[i]);
            float f0 = fs[0][i], f1 = fs[1][i];
            a00 += f0 * wv0; a01 += f0 * wv1;
            a10 += f1 * wv0; a11 += f1 * wv1;
        }
#pragma unroll
        for (int o = 16; o > 0; o >>= 1) {
            a00 += __shfl_xor_sync(0xffffffffu, a00, o);
            a01 += __shfl_xor_sync(0xffffffffu, a01, o);
            a10 += __shfl_xor_sync(0xffffffffu, a10, o);
            a11 += __shfl_xor_sync(0xffffffffu, a11, o);
        }
        if (lane == 0) {
            float bb0 = __ldg(&bias[c0]), bb1 = __ldg(&bias[c1]);
            logits[0][c0] = a00 + bb0; logits[0][c1] = a01 + bb1;
            logits[1][c0] = a10 + bb0; logits[1][c1] = a11 + bb1;
        }
    }

    __syncthreads();   // uniform: logits ready

    if (tid < 2) {
        int b = b0 + tid;
        if (b < B) {
            float m = -1e30f;
#pragma unroll
            for (int c = 0; c < 10; c++) m = fmaxf(m, logits[tid][c]);
            float s = 0.0f;
#pragma unroll
            for (int c = 0; c < 10; c++) s += expf(logits[tid][c] - m);
            float lg = logf(s) + m;
#pragma unroll
            for (int c = 0; c < 10; c++) out[b * 10 + c] = logits[tid][c] - lg;
        }
    }
}

extern "C" void kernel_launch(void* const* d_in, const int* in_sizes, int n_in,
                              void* d_out, int out_size) {
    const float* x    = (const float*)d_in[0];   // (2048, 28, 28)
    const float* vp   = (const float*)d_in[1];   // (2, 2, 4)
    const float* W    = (const float*)d_in[2];   // (10, 784)
    const float* bias = (const float*)d_in[3];   // (10,)
    float* out = (float*)d_out;                  // (2048, 10)

    int B = in_sizes[0] / (IMGd * IMGd);

    quanv_setup_kernel<<<1, 512>>>(vp);
    quanv_main_kernel<<<(B + 1) / 2, THREADS_MAIN>>>(x, W, bias, out, B);
}

// round 14
// speedup vs baseline: 1.2746x; 1.2732x over previous
#include <cuda_runtime.h>
#include <math.h>

// Quanvolution: 4-qubit circuit per 2x2 patch, fixed variational unitary.
// e_w(theta) = sum_t CW[w][t] * prod_q g_{t_q}(theta_q), g = (1, cos, sin).
// CW precomputed by a tiny setup kernel (sparse 16-pair enumeration).
// Main kernel: 2 images/block, P01 inlined from g (register diet), occ >= 4 blocks/SM.

#define NQb 4
#define NPp 196
#define NBp 14
#define IMGd 28
#define THREADS_MAIN 224

// CW stored interleaved: g_CW4[t] = {CW_w0[t], CW_w1[t], CW_w2[t], CW_w3[t]}
__device__ float4 g_CW4[81];

static __device__ __forceinline__ int qbit(int z, int q) { return (z >> (3 - q)) & 1; }

__global__ void quanv_setup_kernel(const float* __restrict__ vp /*[2][2][4]*/) {
    __shared__ float Ur[16][16], Ui[16][16];   // [z][col]
    __shared__ float M[4][16][16];
    int tid = threadIdx.x;

    if (tid < 16) {
        float ar[16], ai[16];
#pragma unroll
        for (int z = 0; z < 16; z++) { ar[z] = (z == tid) ? 1.0f : 0.0f; ai[z] = 0.0f; }
#pragma unroll
        for (int l = 0; l < 2; l++) {
            // RY layer
#pragma unroll
            for (int w = 0; w < 4; w++) {
                float h = 0.5f * vp[l * 8 + w];
                float c, s; __sincosf(h, &s, &c);
                int mask = 8 >> w;
#pragma unroll
                for (int z = 0; z < 16; z++) {
                    if (!(z & mask)) {
                        int z1 = z | mask;
                        float r0 = ar[z], i0 = ai[z], r1 = ar[z1], i1 = ai[z1];
                        ar[z]  = c * r0 - s * r1;  ai[z]  = c * i0 - s * i1;
                        ar[z1] = s * r0 + c * r1;  ai[z1] = s * i0 + c * i1;
                    }
                }
            }
            // RZ layer
#pragma unroll
            for (int w = 0; w < 4; w++) {
                float h = 0.5f * vp[l * 8 + 4 + w];
                float c, s; __sincosf(h, &s, &c);
                int mask = 8 >> w;
#pragma unroll
                for (int z = 0; z < 16; z++) {
                    float ph_i = (z & mask) ? s : -s;   // exp(+-i h)
                    float r = ar[z], im = ai[z];
                    ar[z] = c * r - ph_i * im;
                    ai[z] = c * im + ph_i * r;
                }
            }
            // CNOT chain 0->1, 1->2, 2->3
#pragma unroll
            for (int cq = 0; cq < 3; cq++) {
                int cm = 8 >> cq, tm = 8 >> (cq + 1);
#pragma unroll
                for (int z = 0; z < 16; z++) {
                    if ((z & cm) && !(z & tm)) {
                        int z1 = z | tm;
                        float tr = ar[z], ti = ai[z];
                        ar[z] = ar[z1]; ai[z] = ai[z1];
                        ar[z1] = tr;    ai[z1] = ti;
                    }
                }
            }
        }
#pragma unroll
        for (int z = 0; z < 16; z++) { Ur[z][tid] = ar[z]; Ui[z][tid] = ai[z]; }
    }
    __syncthreads();

    // M[w][i][j] = sum_z sign_w(z) * Re(conj(U[z,i]) U[z,j])
    for (int k = tid; k < 4 * 256; k += blockDim.x) {
        int w = k >> 8, i = (k >> 4) & 15, j = k & 15;
        float acc = 0.0f;
#pragma unroll
        for (int z = 0; z < 16; z++) {
            float sgn = qbit(z, w) ? -1.0f : 1.0f;
            acc += sgn * (Ur[z][i] * Ur[z][j] + Ui[z][i] * Ui[z][j]);
        }
        M[w][i][j] = acc;
    }
    __syncthreads();

    // Sparse contraction: for fixed t, kcoef is nonzero for exactly 2 (bi,bj)
    // combos per qubit -> 16 contributing (i,j) pairs (not 256).
    for (int k = tid; k < 4 * 81; k += blockDim.x) {
        int w = k / 81, t = k % 81;
        int td[4] = { t / 27, (t / 9) % 3, (t / 3) % 3, t % 3 };
        float acc = 0.0f;
#pragma unroll
        for (int m = 0; m < 16; m++) {
            int i = 0, j = 0;
            float coef = 1.0f;
#pragma unroll
            for (int q = 0; q < 4; q++) {
                int sel = (m >> (3 - q)) & 1;
                int tq = td[q];
                int bi, bj; float c;
                if (tq == 2) { bi = sel; bj = 1 - sel; c = 0.5f; }
                else         { bi = sel; bj = sel;
                               c = (tq == 0) ? 0.5f : (sel ? -0.5f : 0.5f); }
                i |= bi << (3 - q);
                j |= bj << (3 - q);
                coef *= c;
            }
            acc += M[w][i][j] * coef;
        }
        ((float*)g_CW4)[t * 4 + w] = acc;   // interleaved layout [t][w]
    }
}

__global__ void __launch_bounds__(THREADS_MAIN, 4) quanv_main_kernel(
    const float* __restrict__ x, const float* __restrict__ W,
    const float* __restrict__ bias, float* __restrict__ out, int B) {
    __shared__ __align__(16) float4 cw4[81];
    __shared__ __align__(16) float fs[2][784];
    __shared__ float logits[2][10];

    int b0 = blockIdx.x * 2;
    int b1 = (b0 + 1 < B) ? (b0 + 1) : b0;       // clamp (duplicate work, guarded write)
    int tid = threadIdx.x;

    if (tid < 81) cw4[tid] = g_CW4[tid];

    int p = tid;
    bool active = (p < NPp);

    // ---- phase 1: guarded loads + g/P23 construction (no barriers here) ----
    // P01 is NOT materialized: pua = g0[u/3]*g1[u%3] inlined in the unrolled loop.
    float g0a[3], g1a[3], P23a[9];
    float g0b[3], g1b[3], P23b[9];
    if (active) {
        int pi = p / NBp, pj = p % NBp;
        int off = pi * 2 * IMGd + pj * 2;

        // coalesced direct global loads: consecutive pj -> contiguous float2
        float2 r0a = __ldg((const float2*)(x + b0 * 784 + off));
        float2 r1a = __ldg((const float2*)(x + b0 * 784 + off + IMGd));
        float2 r0b = __ldg((const float2*)(x + b1 * 784 + off));
        float2 r1b = __ldg((const float2*)(x + b1 * 784 + off + IMGd));

        g0a[0] = 1.0f; __sincosf(r0a.x, &g0a[2], &g0a[1]);
        g1a[0] = 1.0f; __sincosf(r0a.y, &g1a[2], &g1a[1]);
        g0b[0] = 1.0f; __sincosf(r0b.x, &g0b[2], &g0b[1]);
        g1b[0] = 1.0f; __sincosf(r0b.y, &g1b[2], &g1b[1]);

        {
            float g2a[3], g3a[3], g2b[3], g3b[3];
            g2a[0] = 1.0f; __sincosf(r1a.x, &g2a[2], &g2a[1]);
            g3a[0] = 1.0f; __sincosf(r1a.y, &g3a[2], &g3a[1]);
            g2b[0] = 1.0f; __sincosf(r1b.x, &g2b[2], &g2b[1]);
            g3b[0] = 1.0f; __sincosf(r1b.y, &g3b[2], &g3b[1]);
#pragma unroll
            for (int a = 0; a < 3; a++)
#pragma unroll
                for (int c = 0; c < 3; c++) {
                    P23a[a * 3 + c] = g2a[a] * g3a[c];
                    P23b[a * 3 + c] = g2b[a] * g3b[c];
                }
        }
    }

    __syncthreads();   // uniform: cw4 staging complete

    // ---- phase 2: trilinear contraction for both images ----
    if (active) {
        float ax0 = 0.f, ay0 = 0.f, az0 = 0.f, aw0 = 0.f;
        float ax1 = 0.f, ay1 = 0.f, az1 = 0.f, aw1 = 0.f;
#pragma unroll
        for (int u = 0; u < 9; u++) {
            float tx0 = 0.f, ty0 = 0.f, tz0 = 0.f, tw0 = 0.f;
            float tx1 = 0.f, ty1 = 0.f, tz1 = 0.f, tw1 = 0.f;
#pragma unroll
            for (int v = 0; v < 9; v++) {
                float4 c4 = cw4[u * 9 + v];
                float pa = P23a[v], pb = P23b[v];
                tx0 += c4.x * pa; ty0 += c4.y * pa; tz0 += c4.z * pa; tw0 += c4.w * pa;
                tx1 += c4.x * pb; ty1 += c4.y * pb; tz1 += c4.z * pb; tw1 += c4.w * pb;
            }
            float pua = g0a[u / 3] * g1a[u % 3];   // constant indices after unroll
            float pub = g0b[u / 3] * g1b[u % 3];
            ax0 += pua * tx0; ay0 += pua * ty0; az0 += pua * tz0; aw0 += pua * tw0;
            ax1 += pub * tx1; ay1 += pub * ty1; az1 += pub * tz1; aw1 += pub * tw1;
        }
        reinterpret_cast<float4*>(fs[0])[p] = make_float4(ax0, ay0, az0, aw0);
        reinterpret_cast<float4*>(fs[1])[p] = make_float4(ax1, ay1, az1, aw1);
    }

    __syncthreads();   // uniform: features ready

    int warp = tid >> 5, lane = tid & 31;
    if (warp < 5) {
        int c0 = warp * 2, c1 = c0 + 1;
        const float* w0 = &W[c0 * 784];
        const float* w1 = &W[c1 * 784];
        float a00 = 0.f, a01 = 0.f, a10 = 0.f, a11 = 0.f;
#pragma unroll 4
        for (int i = lane; i < 784; i += 32) {
            float wv0 = __ldg(&w0[i]), wv1 = __ldg(&w1[i]);
            float f0 = fs[0][i], f1 = fs[1][i];
            a00 += f0 * wv0; a01 += f0 * wv1;
            a10 += f1 * wv0; a11 += f1 * wv1;
        }
#pragma unroll
        for (int o = 16; o > 0; o >>= 1) {
            a00 += __shfl_xor_sync(0xffffffffu, a00, o);
            a01 += __shfl_xor_sync(0xffffffffu, a01, o);
            a10 += __shfl_xor_sync(0xffffffffu, a10, o);
            a11 += __shfl_xor_sync(0xffffffffu, a11, o);
        }
        if (lane == 0) {
            float bb0 = __ldg(&bias[c0]), bb1 = __ldg(&bias[c1]);
            logits[0][c0] = a00 + bb0; logits[0][c1] = a01 + bb1;
            logits[1][c0] = a10 + bb0; logits[1][c1] = a11 + bb1;
        }
    }

    __syncthreads();   // uniform: logits ready

    if (tid < 2) {
        int b = b0 + tid;
        if (b < B) {
            float m = -1e30f;
#pragma unroll
            for (int c = 0; c < 10; c++) m = fmaxf(m, logits[tid][c]);
            float s = 0.0f;
#pragma unroll
            for (int c = 0; c < 10; c++) s += expf(logits[tid][c] - m);
            float lg = logf(s) + m;
#pragma unroll
            for (int c = 0; c < 10; c++) out[b * 10 + c] = logits[tid][c] - lg;
        }
    }
}

extern "C" void kernel_launch(void* const* d_in, const int* in_sizes, int n_in,
                              void* d_out, int out_size) {
    const float* x    = (const float*)d_in[0];   // (2048, 28, 28)
    const float* vp   = (const float*)d_in[1];   // (2, 2, 4)
    const float* W    = (const float*)d_in[2];   // (10, 784)
    const float* bias = (const float*)d_in[3];   // (10,)
    float* out = (float*)d_out;                  // (2048, 10)

    int B = in_sizes[0] / (IMGd * IMGd);

    quanv_setup_kernel<<<1, 512>>>(vp);
    quanv_main_kernel<<<(B + 1) / 2, THREADS_MAIN>>>(x, W, bias, out, B);
}